// round 3
// baseline (speedup 1.0000x reference)
#include <cuda_runtime.h>
#include <stdint.h>

#define NSEG   16384
#define SEGLEN 1024
#define KSEL   128
#define NTHR   128
#define EPT    8          // elements per thread (2x float4)

// kth-largest (k=128 of 1024 U(0,1)) = 0.875 +- 0.0103. Band is +-3.4 sigma.
#define T_HI   0.91f
#define T_LO   0.84f
#define GBUF   160        // band count: mean ~72, std ~8.2 -> +10 sigma headroom
#define NSLOT  256

__device__ float g_part[NSLOT];   // zero-initialized at module load

__device__ __forceinline__ float warpSumF(float v) {
    #pragma unroll
    for (int o = 16; o; o >>= 1) v += __shfl_down_sync(0xffffffffu, v, o);
    return v;
}
__device__ __forceinline__ int warpSumI(int v) {
    #pragma unroll
    for (int o = 16; o; o >>= 1) v += __shfl_down_sync(0xffffffffu, v, o);
    return v;
}

__global__ __launch_bounds__(NTHR)
void mil_seg_kernel(const float* __restrict__ y_pred, const float* __restrict__ y,
                    int seg_base) {
    __shared__ float s_g[GBUF];
    __shared__ int   s_gc;
    __shared__ float s_rf[4];
    __shared__ int   s_ri[4];
    __shared__ float s_SHI, s_t;
    __shared__ int   s_r, s_m, s_flag;
    __shared__ int   s_itmp[4];
    __shared__ float s_ftmp[4];
    __shared__ int   s_total;

    const int tid  = threadIdx.x;
    const int lane = tid & 31;
    const int wid  = tid >> 5;
    const int seg  = seg_base + blockIdx.x;

    const float4* base = reinterpret_cast<const float4*>(y_pred + (size_t)seg * SEGLEN);
    const float4 a4 = base[tid];
    const float4 b4 = base[tid + NTHR];
    if (tid == 0) { s_gc = 0; s_t = __ldg(y + (size_t)seg * SEGLEN); }
    __syncthreads();   // s_gc ready before gather atomics

    float v[EPT] = {a4.x, a4.y, a4.z, a4.w, b4.x, b4.y, b4.z, b4.w};

    // classify: count/sum above T_HI; warp-aggregated gather of band [T_LO, T_HI)
    int   c_hi = 0;
    float f_hi = 0.f;
    #pragma unroll
    for (int j = 0; j < EPT; j++) {
        float x = v[j];
        bool hi   = (x >= T_HI);
        bool band = (x >= T_LO) && !hi;
        if (hi) { c_hi++; f_hi += x; }
        unsigned mask = __ballot_sync(0xffffffffu, band);
        if (mask) {
            int ldr = __ffs(mask) - 1;
            int cnt = __popc(mask);
            int bse = 0;
            if (lane == ldr) bse = atomicAdd(&s_gc, cnt);
            bse = __shfl_sync(0xffffffffu, bse, ldr);
            if (band) {
                int pos = bse + __popc(mask & ((1u << lane) - 1u));
                if (pos < GBUF) s_g[pos] = x;
            }
        }
    }

    // block reduce c_hi / f_hi (4 warps)
    {
        float r1 = warpSumF(f_hi);
        int   ri = warpSumI(c_hi);
        if (lane == 0) { s_rf[wid] = r1; s_ri[wid] = ri; }
    }
    __syncthreads();   // also guarantees s_g fully written

    if (tid == 0) {
        float SHI = s_rf[0] + s_rf[1] + s_rf[2] + s_rf[3];
        int   CHI = s_ri[0] + s_ri[1] + s_ri[2] + s_ri[3];
        int   m   = s_gc;
        s_SHI = SHI;
        s_m   = m;
        s_r   = KSEL - CHI;
        s_flag = (CHI > KSEL || CHI + m < KSEL || m > GBUF) ? 1 : 0;
    }
    __syncthreads();

    if (!s_flag) {
        // -------- fast path: exact rank of band elements (parallel, LDS broadcast)
        const int m = s_m;
        const int r = s_r;          // 0 <= r <= m
        float bsum = 0.f;
        if (tid < m && r > 0) {
            unsigned mb = __float_as_uint(s_g[tid]);  // positive floats: int order
            int rank = 0;
            for (int j = 0; j < m; j++) {
                unsigned xb = __float_as_uint(s_g[j]);
                rank += (xb > mb) || (xb == mb && j < tid);
            }
            if (rank < r) bsum = __uint_as_float(mb);
        }
        {
            float rb = warpSumF(bsum);
            if (lane == 0) s_rf[wid] = rb;
        }
        __syncthreads();
        if (tid == 0) {
            float bs = s_rf[0] + s_rf[1] + s_rf[2] + s_rf[3];
            float p = (s_SHI + bs) * (1.0f / KSEL);
            float t = s_t;
            atomicAdd(&g_part[seg & (NSLOT - 1)],
                      t * logf(p) + (1.0f - t) * log1pf(-p));
        }
    } else {
        // -------- exact fallback: bitwise radix select over full segment
        unsigned u[EPT];
        #pragma unroll
        for (int j = 0; j < EPT; j++) u[j] = __float_as_uint(v[j]);

        unsigned prefix = 0;
        for (int bit = 30; bit >= 0; bit--) {
            unsigned test = prefix | (1u << bit);
            int c = 0;
            #pragma unroll
            for (int j = 0; j < EPT; j++) c += (u[j] >= test);
            c = warpSumI(c);
            if (lane == 0) s_itmp[wid] = c;
            __syncthreads();
            if (tid == 0) s_total = s_itmp[0] + s_itmp[1] + s_itmp[2] + s_itmp[3];
            __syncthreads();
            if (s_total >= KSEL) prefix = test;
            __syncthreads();
        }
        int   g = 0;
        float s = 0.f;
        #pragma unroll
        for (int j = 0; j < EPT; j++) {
            if (u[j] > prefix) { g++; s += v[j]; }
        }
        s = warpSumF(s);
        g = warpSumI(g);
        if (lane == 0) { s_ftmp[wid] = s; s_itmp[wid] = g; }
        __syncthreads();
        if (tid == 0) {
            float S = s_ftmp[0] + s_ftmp[1] + s_ftmp[2] + s_ftmp[3];
            int   G = s_itmp[0] + s_itmp[1] + s_itmp[2] + s_itmp[3];
            float kthv = __uint_as_float(prefix);
            float p = (S + (float)(KSEL - G) * kthv) * (1.0f / KSEL);
            float t = s_t;
            atomicAdd(&g_part[seg & (NSLOT - 1)],
                      t * logf(p) + (1.0f - t) * log1pf(-p));
        }
    }
}

__global__ __launch_bounds__(NSLOT)
void mil_finalize_kernel(float* __restrict__ out) {
    __shared__ float sp[8];
    const int tid = threadIdx.x;
    float s = g_part[tid];
    g_part[tid] = 0.0f;               // reset for next graph replay
    s = warpSumF(s);
    if ((tid & 31) == 0) sp[tid >> 5] = s;
    __syncthreads();
    if (tid == 0) {
        float t = 0.f;
        #pragma unroll
        for (int w = 0; w < 8; w++) t += sp[w];
        out[0] = -t * (1.0f / NSEG);
    }
}

extern "C" void kernel_launch(void* const* d_in, const int* in_sizes, int n_in,
                              void* d_out, int out_size) {
    const float* y_pred = (const float*)d_in[0];
    const float* yv     = (const float*)d_in[1];
    (void)in_sizes; (void)n_in; (void)out_size;

    // 3-way split: 4 launches/call so ncu's fixed capture index lands on a
    // seg kernel (profiling instrumentation; ~1us launch overhead).
    const int g1 = 5462, g2 = 5462, g3 = NSEG - g1 - g2;
    mil_seg_kernel<<<g1, NTHR>>>(y_pred, yv, 0);
    mil_seg_kernel<<<g2, NTHR>>>(y_pred, yv, g1);
    mil_seg_kernel<<<g3, NTHR>>>(y_pred, yv, g1 + g2);
    mil_finalize_kernel<<<1, NSLOT>>>((float*)d_out);
}

// round 5
// speedup vs baseline: 1.5417x; 1.5417x over previous
#include <cuda_runtime.h>
#include <stdint.h>

#define NSEG   16384
#define SEGLEN 1024
#define KSEL   128
#define NTHR   256
#define EPT    4

// kth-largest (k=128 of 1024 U(0,1)) = 0.875 +- 0.0103.
// Band [0.80, 0.93) in 127 bins; bin 127 = overflow (x >= 0.93).
#define T_LO   0.80f
#define T_HI   0.93f
#define NBAND  127
#define NBTOT  128
#define INV_W  ((float)NBAND / (T_HI - T_LO))
#define GBUF   64
#define NSLOT  256

__device__ float    g_part[NSLOT];   // zero-initialized at module load
__device__ unsigned g_done = 0;

__device__ __forceinline__ float warpSumF(float v) {
    #pragma unroll
    for (int o = 16; o; o >>= 1) v += __shfl_down_sync(0xffffffffu, v, o);
    return v;
}
__device__ __forceinline__ int warpSumI(int v) {
    #pragma unroll
    for (int o = 16; o; o >>= 1) v += __shfl_down_sync(0xffffffffu, v, o);
    return v;
}

__global__ __launch_bounds__(NTHR)
void mil_fused_kernel(const float* __restrict__ y_pred, const float* __restrict__ y,
                      float* __restrict__ out) {
    __shared__ int   s_hist[NBTOT];
    __shared__ float s_g[GBUF];
    __shared__ int   s_gc;
    __shared__ float s_rf[8];
    __shared__ float s_t;
    __shared__ int   s_flag, s_bstar, s_above, s_m;
    __shared__ int   s_itmp[8];
    __shared__ float s_ftmp[8];
    __shared__ int   s_total;
    __shared__ int   s_islast;

    const int tid  = threadIdx.x;
    const int lane = tid & 31;
    const int wid  = tid >> 5;
    const int seg  = blockIdx.x;

    const float4 v4 = reinterpret_cast<const float4*>(y_pred + (size_t)seg * SEGLEN)[tid];
    if (tid == 0) { s_gc = 0; s_t = __ldg(y + (size_t)seg * SEGLEN); }
    if (tid < NBTOT) s_hist[tid] = 0;
    __syncthreads();

    float v[EPT] = {v4.x, v4.y, v4.z, v4.w};

    // ---- pass 1: counts-only histogram (25% of elements take one ATOMS) ----
    #pragma unroll
    for (int j = 0; j < EPT; j++) {
        float x = v[j];
        if (x >= T_LO) {
            int b = min((int)((x - T_LO) * INV_W), NBAND);
            atomicAdd(&s_hist[b], 1);
        }
    }
    __syncthreads();

    // ---- warp 0: suffix scan, locate boundary bin b* (counts only) ----
    if (wid == 0) {
        int cb[4];
        #pragma unroll
        for (int i = 0; i < 4; i++) cb[i] = s_hist[4 * lane + i];
        int own = (cb[0] + cb[1]) + (cb[2] + cb[3]);
        int inc = own;
        #pragma unroll
        for (int o = 1; o < 32; o <<= 1) {
            int t = __shfl_down_sync(0xffffffffu, inc, o);
            if (lane + o < 32) inc += t;
        }
        const int exc   = inc - own;
        const int total = __shfl_sync(0xffffffffu, inc, 0);
        if (lane == 0) s_flag = (total < KSEL) ? 1 : 0;

        const bool here = (exc < KSEL) && (KSEL <= inc);   // exactly one lane
        if (here) {
            int cum = exc, bstar = -1, above = 0, mcnt = 0;
            #pragma unroll
            for (int i = 3; i >= 0; i--) {
                if (bstar < 0) {
                    if (cum + cb[i] >= KSEL) { bstar = 4 * lane + i; above = cum; mcnt = cb[i]; }
                    else cum += cb[i];
                }
            }
            s_bstar = bstar; s_above = above; s_m = mcnt;
        }
        __syncwarp();
        if (here && s_m > GBUF) s_flag = 1;
    }
    __syncthreads();

    float loss = 0.f;   // valid on tid 0 only

    if (!s_flag) {
        // ---- pass 2 (registers): sum above b*, gather boundary-bin elements ----
        const int bstar = s_bstar;
        float sa = 0.f;
        #pragma unroll
        for (int j = 0; j < EPT; j++) {
            float x = v[j];
            if (x >= T_LO) {
                int b = min((int)((x - T_LO) * INV_W), NBAND);
                if (b > bstar) sa += x;
                else if (b == bstar) {
                    int idx = atomicAdd(&s_gc, 1);
                    if (idx < GBUF) s_g[idx] = x;
                }
            }
        }
        __syncthreads();   // gather complete

        // exact top-r of boundary bin (m ~ 1-3 expected), fold into same reduce
        const int m = s_m;
        const int r = KSEL - s_above;        // 1 <= r <= m
        if (tid < m) {
            unsigned mb = __float_as_uint(s_g[tid]);   // positive: int order
            int rank = 0;
            for (int j = 0; j < m; j++) {
                unsigned xb = __float_as_uint(s_g[j]);
                rank += (xb > mb) || (xb == mb && j < tid);
            }
            if (rank < r) sa += __uint_as_float(mb);
        }
        {
            float rs = warpSumF(sa);
            if (lane == 0) s_rf[wid] = rs;
        }
        __syncthreads();
        if (tid == 0) {
            float S = 0.f;
            #pragma unroll
            for (int w = 0; w < 8; w++) S += s_rf[w];
            float p = S * (1.0f / KSEL);
            float t = s_t;
            loss = t * logf(p) + (1.0f - t) * log1pf(-p);
        }
    } else {
        // ---- exact fallback: bitwise radix select over full segment ----
        unsigned u[EPT];
        #pragma unroll
        for (int j = 0; j < EPT; j++) u[j] = __float_as_uint(v[j]);

        unsigned prefix = 0;
        for (int bit = 30; bit >= 0; bit--) {
            unsigned test = prefix | (1u << bit);
            int c = 0;
            #pragma unroll
            for (int j = 0; j < EPT; j++) c += (u[j] >= test);
            c = warpSumI(c);
            if (lane == 0) s_itmp[wid] = c;
            __syncthreads();
            if (tid == 0) {
                int cc = 0;
                #pragma unroll
                for (int w = 0; w < 8; w++) cc += s_itmp[w];
                s_total = cc;
            }
            __syncthreads();
            if (s_total >= KSEL) prefix = test;
            __syncthreads();
        }
        int   g = 0;
        float s = 0.f;
        #pragma unroll
        for (int j = 0; j < EPT; j++) {
            if (u[j] > prefix) { g++; s += v[j]; }
        }
        s = warpSumF(s);
        g = warpSumI(g);
        if (lane == 0) { s_ftmp[wid] = s; s_itmp[wid] = g; }
        __syncthreads();
        if (tid == 0) {
            float S = 0.f; int G = 0;
            #pragma unroll
            for (int w = 0; w < 8; w++) { S += s_ftmp[w]; G += s_itmp[w]; }
            float kthv = __uint_as_float(prefix);
            float p = (S + (float)(KSEL - G) * kthv) * (1.0f / KSEL);
            float t = s_t;
            loss = t * logf(p) + (1.0f - t) * log1pf(-p);
        }
    }

    // ---- fused finalize: last block reduces the 256 partials ----
    if (tid == 0) {
        atomicAdd(&g_part[seg & (NSLOT - 1)], loss);
        __threadfence();
        unsigned old = atomicAdd(&g_done, 1u);
        s_islast = (old == NSEG - 1) ? 1 : 0;
    }
    __syncthreads();
    if (s_islast) {
        __threadfence();
        float sv = g_part[tid];       // NTHR == NSLOT
        g_part[tid] = 0.0f;           // reset for next graph replay
        sv = warpSumF(sv);
        if (lane == 0) s_rf[wid] = sv;
        __syncthreads();
        if (tid == 0) {
            float t = 0.f;
            #pragma unroll
            for (int w = 0; w < 8; w++) t += s_rf[w];
            out[0] = -t * (1.0f / NSEG);
            g_done = 0;               // reset for next graph replay
        }
    }
}

extern "C" void kernel_launch(void* const* d_in, const int* in_sizes, int n_in,
                              void* d_out, int out_size) {
    const float* y_pred = (const float*)d_in[0];
    const float* yv     = (const float*)d_in[1];
    (void)in_sizes; (void)n_in; (void)out_size;

    mil_fused_kernel<<<NSEG, NTHR>>>(y_pred, yv, (float*)d_out);
}

// round 7
// speedup vs baseline: 1.9103x; 1.2391x over previous
#include <cuda_runtime.h>
#include <stdint.h>

#define NSEG   16384
#define SEGLEN 1024
#define KSEL   128
#define NTHR   256
#define WPB    8
#define NBLK   (NSEG / WPB)

// f = x*1280 - 1075.2  maps x in [0.84, 0.915) -> f in [0, 96)
#define INV_W  1280.0f
#define F_C    (-1075.2f)
#define NBANDF 96.0f
#define NBAND  96
#define SLOTS  12      // per-lane gather slots (band count/lane ~ Bin(32,.075))
#define BBUFN  8       // boundary-bin buffer
#define NSLOT  256

__device__ float    g_part[NSLOT];   // zero-init at load
__device__ unsigned g_done = 0;

#define FULLM 0xffffffffu

__device__ __forceinline__ float warpSumF(float v) {
    #pragma unroll
    for (int o = 16; o; o >>= 1) v += __shfl_xor_sync(FULLM, v, o);
    return v;   // all lanes get the sum
}

__global__ __launch_bounds__(NTHR)
void mil_kernel(const float* __restrict__ y_pred, const float* __restrict__ y,
                float* __restrict__ out) {
    __shared__ int   s_hist[WPB][NBAND];
    __shared__ float s_gath[WPB][SLOTS * 32];
    __shared__ float s_bbuf[WPB][BBUFN];
    __shared__ int   s_bcnt[WPB];
    __shared__ int   s_fb[WPB];
    __shared__ float s_red[WPB];
    __shared__ int   s_islast;

    const int tid  = threadIdx.x;
    const int lane = tid & 31;
    const int w    = tid >> 5;
    const int seg  = blockIdx.x * WPB + w;

    // warp-local init (no block barrier anywhere in the hot path)
    s_hist[w][lane] = 0; s_hist[w][lane + 32] = 0; s_hist[w][lane + 64] = 0;
    if (lane == 0) { s_bcnt[w] = 0; s_fb[w] = 0; }
    __syncwarp();

    const float4* base = reinterpret_cast<const float4*>(y_pred + (size_t)seg * SEGLEN);
    const float t = __ldg(y + (size_t)seg * SEGLEN);   // label: segment-constant

    int*   hist = &s_hist[w][0];
    float* gath = &s_gath[w][0];

    int   c_hi = 0;
    float s_hi = 0.f;
    int   cnt  = 0;

    // ---- pass 1: stream 32 elems/thread, double-buffered float4 loads ----
    float4 cur = base[lane];
    #pragma unroll
    for (int c = 0; c < 8; c++) {
        float4 nxt;
        if (c < 7) nxt = base[lane + (c + 1) * 32];
        float xs[4] = {cur.x, cur.y, cur.z, cur.w};
        #pragma unroll
        for (int j = 0; j < 4; j++) {
            float x = xs[j];
            float f = fmaf(x, INV_W, F_C);
            if (f >= NBANDF) { c_hi++; s_hi += x; }
            else if (f >= 0.0f) {
                int b = (int)f;                       // 0..95
                atomicAdd(&hist[b], 1);
                if (cnt < SLOTS) gath[lane + cnt * 32] = x;
                cnt++;
            }
        }
        cur = nxt;
    }
    if (cnt > SLOTS) s_fb[w] = 1;                     // benign race (all write 1)
    __syncwarp();                                     // hist + fb visible

    // ---- warp reduces (butterfly: result uniform on all lanes) ----
    c_hi = __reduce_add_sync(FULLM, c_hi);
    s_hi = warpSumF(s_hi);
    const int need = KSEL - c_hi;

    // ---- suffix scan of 96-bin counts; locate boundary bin b* ----
    const int c0 = hist[3 * lane], c1 = hist[3 * lane + 1], c2 = hist[3 * lane + 2];
    const int own = c0 + c1 + c2;
    int inc = own;
    #pragma unroll
    for (int o = 1; o < 32; o <<= 1) {
        int v = __shfl_down_sync(FULLM, inc, o);
        if (lane + o < 32) inc += v;
    }
    const int exc   = inc - own;
    const int total = __shfl_sync(FULLM, inc, 0);

    bool fb = (s_fb[w] != 0) || (need <= 0) || (c_hi + total < KSEL);

    int bstar = 0, above = 0;
    {
        bool here = !fb && (exc < need) && (need <= inc);
        int lb = 0, la = 0;
        if (here) {
            if      (exc + c2 >= need)           { lb = 3 * lane + 2; la = exc; }
            else if (exc + c2 + c1 >= need)      { lb = 3 * lane + 1; la = exc + c2; }
            else                                 { lb = 3 * lane;     la = exc + c2 + c1; }
        }
        unsigned bal = __ballot_sync(FULLM, here);
        if (bal == 0) fb = true;
        else {
            int src = __ffs(bal) - 1;
            bstar = __shfl_sync(FULLM, lb, src);
            above = __shfl_sync(FULLM, la, src);
        }
    }

    float loss = 0.f;    // valid on lane 0

    if (!fb) {
        // ---- rescan own gathered slots: sum bins > b*, gather bin == b* ----
        float sa = 0.f;
        for (int k = 0; k < cnt; k++) {
            float x = gath[lane + k * 32];
            int b = (int)fmaf(x, INV_W, F_C);         // same formula -> consistent
            if (b > bstar) sa += x;
            else if (b == bstar) {
                int i2 = atomicAdd(&s_bcnt[w], 1);
                if (i2 < BBUFN) s_bbuf[w][i2] = x;
            }
        }
        __syncwarp();
        const int mm = s_bcnt[w];
        if (mm > BBUFN) fb = true;
        else {
            const int r = need - above;               // 1..mm
            if (lane < mm) {
                unsigned mv = __float_as_uint(s_bbuf[w][lane]);  // positive: int order
                int rk = 0;
                for (int j = 0; j < mm; j++) {
                    unsigned xv = __float_as_uint(s_bbuf[w][j]);
                    rk += (xv > mv) || (xv == mv && j < lane);
                }
                if (rk < r) sa += __uint_as_float(mv);
            }
            sa = warpSumF(sa);
            if (lane == 0) {
                float p = (s_hi + sa) * (1.0f / KSEL);
                loss = t * logf(p) + (1.0f - t) * log1pf(-p);
            }
        }
    }

    if (fb) {
        // ---- exact fallback: radix select, reload from L2 (rare) ----
        unsigned prefix = 0;
        for (int bit = 30; bit >= 0; bit--) {
            unsigned test = prefix | (1u << bit);
            int cc = 0;
            #pragma unroll
            for (int c = 0; c < 8; c++) {
                float4 q = base[lane + c * 32];
                cc += (__float_as_uint(q.x) >= test) + (__float_as_uint(q.y) >= test)
                    + (__float_as_uint(q.z) >= test) + (__float_as_uint(q.w) >= test);
            }
            cc = __reduce_add_sync(FULLM, cc);
            if (cc >= KSEL) prefix = test;
        }
        float S = 0.f; int G = 0;
        #pragma unroll
        for (int c = 0; c < 8; c++) {
            float4 q = base[lane + c * 32];
            if (__float_as_uint(q.x) > prefix) { G++; S += q.x; }
            if (__float_as_uint(q.y) > prefix) { G++; S += q.y; }
            if (__float_as_uint(q.z) > prefix) { G++; S += q.z; }
            if (__float_as_uint(q.w) > prefix) { G++; S += q.w; }
        }
        S = warpSumF(S);
        G = __reduce_add_sync(FULLM, G);
        if (lane == 0) {
            float kthv = __uint_as_float(prefix);
            float p = (S + (float)(KSEL - G) * kthv) * (1.0f / KSEL);
            loss = t * logf(p) + (1.0f - t) * log1pf(-p);
        }
    }

    if (lane == 0) atomicAdd(&g_part[seg & (NSLOT - 1)], loss);

    // ---- fused finalize: last block reduces the 256 partials ----
    __syncthreads();
    if (tid == 0) {
        __threadfence();
        unsigned old = atomicAdd(&g_done, 1u);
        s_islast = (old == NBLK - 1) ? 1 : 0;
    }
    __syncthreads();
    if (s_islast) {
        __threadfence();
        float v = g_part[tid];
        g_part[tid] = 0.0f;                   // reset for next graph replay
        v = warpSumF(v);
        if (lane == 0) s_red[w] = v;
        __syncthreads();
        if (tid == 0) {
            float acc = 0.f;
            #pragma unroll
            for (int i = 0; i < WPB; i++) acc += s_red[i];
            out[0] = -acc * (1.0f / NSEG);
            g_done = 0;                       // reset for next graph replay
        }
    }
}

extern "C" void kernel_launch(void* const* d_in, const int* in_sizes, int n_in,
                              void* d_out, int out_size) {
    const float* y_pred = (const float*)d_in[0];
    const float* yv     = (const float*)d_in[1];
    (void)in_sizes; (void)n_in; (void)out_size;

    mil_kernel<<<NBLK, NTHR>>>(y_pred, yv, (float*)d_out);
}